// round 9
// baseline (speedup 1.0000x reference)
#include <cuda_runtime.h>

typedef unsigned long long u64;
#define FULLMASK 0xffffffffu

// smem matrix stride in u64 units. 34 gives: (a) even stride -> every row start
// 16B aligned (LDS.128/STS.128 legal), (b) A-row strided loads hit 8 distinct
// bank-pairs (rg*34 mod 16 = 2*rg), conflict-free.
#define SS 34

// ---------------- scratch (static device globals; no runtime alloc) ---------
// layouts: [half][chunk/group][pair][32][32], element = float2 packed as u64
__device__ u64 g_chunk[2 * 28 * 64 * 1024];  // 29.4 MB
__device__ u64 g_part [2 * 7  * 64 * 1024];  //  7.3 MB
__device__ u64 g_half [2 * 1  * 64 * 1024];  //  1.0 MB

// ---------------- packed f32x2 helpers --------------------------------------
__device__ __forceinline__ u64 pack2(float x, float y) {
    u64 r; asm("mov.b64 %0,{%1,%2};" : "=l"(r) : "f"(x), "f"(y)); return r;
}
__device__ __forceinline__ void unpack2(u64 v, float &x, float &y) {
    asm("mov.b64 {%0,%1},%2;" : "=f"(x), "=f"(y) : "l"(v));
}
__device__ __forceinline__ void fma2(u64 &c, u64 a, u64 b) {
    asm("fma.rn.f32x2 %0,%1,%2,%0;" : "+l"(c) : "l"(a), "l"(b));
}

// ---------------- warp 32x32 (xf32x2) matmul --------------------------------
// C = A * B.  A, B in smem, row-major, stride SS (u64 units).
// Lane tile: rows {rg, rg+8, rg+16, rg+24}, cols {cg*8 .. cg*8+7}.
__device__ __forceinline__ void mm(const u64 *A, const u64 *B, u64 c[32],
                                   int rg, int cg) {
#pragma unroll
    for (int i = 0; i < 32; i++) c[i] = 0ull;
#pragma unroll 8
    for (int k = 0; k < 32; k++) {
        u64 a0 = A[(rg     ) * SS + k];
        u64 a1 = A[(rg +  8) * SS + k];
        u64 a2 = A[(rg + 16) * SS + k];
        u64 a3 = A[(rg + 24) * SS + k];
        const ulonglong2 *bp = (const ulonglong2 *)&B[k * SS + cg * 8];
        ulonglong2 b0 = bp[0], b1 = bp[1], b2 = bp[2], b3 = bp[3];
        u64 bb[8] = {b0.x, b0.y, b1.x, b1.y, b2.x, b2.y, b3.x, b3.y};
#pragma unroll
        for (int cc = 0; cc < 8; cc++) {
            fma2(c[cc     ], a0, bb[cc]);
            fma2(c[cc +  8], a1, bb[cc]);
            fma2(c[cc + 16], a2, bb[cc]);
            fma2(c[cc + 24], a3, bb[cc]);
        }
    }
}

__device__ __forceinline__ void storeC_smem(u64 *A, const u64 c[32], int rg, int cg) {
#pragma unroll
    for (int t = 0; t < 4; t++)
#pragma unroll
        for (int cc = 0; cc < 8; cc += 2)
            *(ulonglong2 *)&A[(rg + 8 * t) * SS + cg * 8 + cc] =
                make_ulonglong2(c[t * 8 + cc], c[t * 8 + cc + 1]);
}

__device__ __forceinline__ void storeC_gmem(u64 *dst, const u64 c[32], int rg, int cg) {
#pragma unroll
    for (int t = 0; t < 4; t++)
#pragma unroll
        for (int cc = 0; cc < 8; cc += 2)
            *(ulonglong2 *)&dst[(rg + 8 * t) * 32 + cg * 8 + cc] =
                make_ulonglong2(c[t * 8 + cc], c[t * 8 + cc + 1]);
}

// Build per-site, per-batch-pair matrix into smem (stride SS):
//   M = c0 + x * (c1 - c0), packed (batch 2p, batch 2p+1).
// coreSite points at core_tensors[s,:,:,:] viewed as float2 (d contiguous).
__device__ __forceinline__ void buildM(u64 *M, const float2 *__restrict__ coreSite,
                                       float x0, float x1, int lane) {
#pragma unroll
    for (int t = 0; t < 16; t++) {
        int e = t * 64 + lane * 2;                 // element index (i*32+j), even
        float4 cc = *(const float4 *)(coreSite + e);  // (c0,c1) of e and e+1
        float d0 = cc.y - cc.x;
        float d1 = cc.w - cc.z;
        u64 m0 = pack2(fmaf(x0, d0, cc.x), fmaf(x1, d0, cc.x));
        u64 m1 = pack2(fmaf(x0, d1, cc.z), fmaf(x1, d1, cc.z));
        int i = e >> 5, k = e & 31;
        *(ulonglong2 *)&M[i * SS + k] = make_ulonglong2(m0, m1);
    }
}

// ---------------- kernel 1: chunk products ----------------------------------
// grid = 64 pairs * 56 chunks (28 per half, 14 sites each), 1 warp per block.
// sites of chunk hc are [hc*14, hc*14+14)  (half*392 + chunk*14 == hc*14).
__global__ void __launch_bounds__(32)
k_chunks(const float *__restrict__ xin, const float2 *__restrict__ core2) {
    __shared__ u64 Asm[32 * SS];
    __shared__ u64 Bsm[32 * SS];
    int lane = threadIdx.x;
    int rg = lane >> 2, cg = lane & 3;
    int bx = blockIdx.x;
    int pair = bx & 63;
    int hc   = bx >> 6;            // 0..55
    int s0   = hc * 14;

    const float *xr0 = xin + (size_t)(2 * pair) * 784;
    const float *xr1 = xr0 + 784;

    buildM(Asm, core2 + (size_t)s0 * 1024, __ldg(xr0 + s0), __ldg(xr1 + s0), lane);
    __syncwarp();

    u64 c[32];
    for (int step = 1; step < 14; step++) {
        int s = s0 + step;
        buildM(Bsm, core2 + (size_t)s * 1024, __ldg(xr0 + s), __ldg(xr1 + s), lane);
        __syncwarp();
        mm(Asm, Bsm, c, rg, cg);
        __syncwarp();
        if (step < 13) { storeC_smem(Asm, c, rg, cg); __syncwarp(); }
    }
    storeC_gmem(g_chunk + ((size_t)hc * 64 + pair) * 1024, c, rg, cg);
}

// ---------------- kernels 2a/2b: reduce chunk products ----------------------
__device__ __forceinline__ void reduce_body(const u64 *__restrict__ in,
                                            u64 *__restrict__ out,
                                            int nPer, int nGroups) {
    __shared__ u64 Asm[32 * SS];
    __shared__ u64 Bsm[32 * SS];
    int lane = threadIdx.x;
    int rg = lane >> 2, cg = lane & 3;
    int bx = blockIdx.x;
    int pair = bx & 63;
    int q    = bx >> 6;
    int g    = q % nGroups;
    int half = q / nGroups;

    const u64 *src0 = in + ((((size_t)(half * nGroups + g)) * nPer + 0) * 64 + pair) * 1024;
#pragma unroll 8
    for (int t = 0; t < 32; t++) Asm[t * SS + lane] = src0[t * 32 + lane];
    __syncwarp();

    u64 c[32];
    for (int m = 1; m < nPer; m++) {
        const u64 *srcm = in + ((((size_t)(half * nGroups + g)) * nPer + m) * 64 + pair) * 1024;
#pragma unroll 8
        for (int t = 0; t < 32; t++) Bsm[t * SS + lane] = srcm[t * 32 + lane];
        __syncwarp();
        mm(Asm, Bsm, c, rg, cg);
        __syncwarp();
        if (m < nPer - 1) { storeC_smem(Asm, c, rg, cg); __syncwarp(); }
    }
    storeC_gmem(out + (((size_t)half * nGroups + g) * 64 + pair) * 1024, c, rg, cg);
}

__global__ void __launch_bounds__(32) k_reduce_a() { reduce_body(g_chunk, g_part, 4, 7); }
__global__ void __launch_bounds__(32) k_reduce_b() { reduce_body(g_part,  g_half, 7, 1); }

// ---------------- kernel 3: scores ------------------------------------------
// scores[b,l] = sum_{i,j,k} left[b,i,j] * label[j,k,l] * right[b,k,i]
// One block per batch-pair (64), 10 warps = 10 labels.
__global__ void __launch_bounds__(320)
k_scores(const float *__restrict__ label, float *__restrict__ out) {
    int pair = blockIdx.x;
    int l    = threadIdx.x >> 5;        // 0..9
    int lane = threadIdx.x & 31;
    int rg = lane >> 2, cg = lane & 3;
    const u64 *left  = g_half + ((size_t)0 * 64 + pair) * 1024;
    const u64 *right = g_half + ((size_t)1 * 64 + pair) * 1024;

    // P = left * L_l   (A from gmem, broadcast-friendly; B scalar, duplicated)
    u64 c[32];
#pragma unroll
    for (int i = 0; i < 32; i++) c[i] = 0ull;
#pragma unroll 4
    for (int j = 0; j < 32; j++) {
        u64 a0 = __ldg(&left[(rg     ) * 32 + j]);
        u64 a1 = __ldg(&left[(rg +  8) * 32 + j]);
        u64 a2 = __ldg(&left[(rg + 16) * 32 + j]);
        u64 a3 = __ldg(&left[(rg + 24) * 32 + j]);
        u64 bb[8];
#pragma unroll
        for (int cc = 0; cc < 8; cc++) {
            float v = __ldg(&label[(size_t)j * 320 + (cg * 8 + cc) * 10 + l]);
            bb[cc] = pack2(v, v);
        }
#pragma unroll
        for (int cc = 0; cc < 8; cc++) {
            fma2(c[cc     ], a0, bb[cc]);
            fma2(c[cc +  8], a1, bb[cc]);
            fma2(c[cc + 16], a2, bb[cc]);
            fma2(c[cc + 24], a3, bb[cc]);
        }
    }

    // trace(P * right) : acc += P[row][col] * right[col][row]
    u64 acc = 0ull;
#pragma unroll
    for (int t = 0; t < 4; t++)
#pragma unroll
        for (int cc = 0; cc < 8; cc++) {
            int row = rg + 8 * t, col = cg * 8 + cc;
            u64 r = __ldg(&right[col * 32 + row]);
            fma2(acc, c[t * 8 + cc], r);
        }

    float sx, sy; unpack2(acc, sx, sy);
#pragma unroll
    for (int off = 16; off; off >>= 1) {
        sx += __shfl_xor_sync(FULLMASK, sx, off);
        sy += __shfl_xor_sync(FULLMASK, sy, off);
    }
    if (lane == 0) {
        out[(2 * pair    ) * 10 + l] = sx;
        out[(2 * pair + 1) * 10 + l] = sy;
    }
}

// ---------------- launcher ---------------------------------------------------
extern "C" void kernel_launch(void *const *d_in, const int *in_sizes, int n_in,
                              void *d_out, int out_size) {
    const float  *xin   = (const float  *)d_in[0];   // (128, 784)
    const float2 *core2 = (const float2 *)d_in[1];   // (784, 32, 32, 2) -> float2 over d
    const float  *label = (const float  *)d_in[2];   // (32, 32, 10)
    float *out = (float *)d_out;                     // (128, 10)

    k_chunks  <<<64 * 56,  32>>>(xin, core2);
    k_reduce_a<<<2 * 7 * 64, 32>>>();
    k_reduce_b<<<2 * 64,     32>>>();
    k_scores  <<<64,        320>>>(label, out);
}